// round 13
// baseline (speedup 1.0000x reference)
#include <cuda_runtime.h>
#include <cuda_fp16.h>
#include <cstdint>

#define BATCH 4
#define DIM   512
#define HEADS 8
#define DHEAD 64
#define HW    4096
#define LKV   1024

// fp16 scratch (device globals; allocation-free)
__device__ __half g_wq [512 * 512];
__device__ __half g_wkv[1024 * 2048];
__device__ __half g_wo [512 * 512];
__device__ __half g_xt [BATCH * HW * DIM];     // x^T    [b][pos][ch]
__device__ __half g_x2 [BATCH * LKV * 2048];   // im2col [b][n][k]
__device__ __half g_q  [BATCH * DIM * HW];     // Q      [b][ch][pos]
__device__ __half g_kv [BATCH * 2 * DIM * LKV];// KV     [b][och][ij]
__device__ __half g_ot [BATCH * HW * DIM];     // attnO^T[b][pos][ch]

// ---------------- helpers ----------------
__device__ __forceinline__ uint32_t packh2(float lo, float hi) {
    uint32_t r;
    asm("cvt.rn.f16x2.f32 %0, %1, %2;" : "=r"(r) : "f"(hi), "f"(lo));
    return r;
}
__device__ __forceinline__ uint32_t smem_u32(const void* p) {
    uint32_t a;
    asm("{ .reg .u64 t; cvta.to.shared.u64 t, %1; cvt.u32.u64 %0, t; }" : "=r"(a) : "l"(p));
    return a;
}
__device__ __forceinline__ void ldsm4(uint32_t& r0, uint32_t& r1, uint32_t& r2, uint32_t& r3,
                                      uint32_t addr) {
    asm volatile("ldmatrix.sync.aligned.m8n8.x4.shared.b16 {%0,%1,%2,%3}, [%4];"
                 : "=r"(r0), "=r"(r1), "=r"(r2), "=r"(r3) : "r"(addr));
}
__device__ __forceinline__ void ldsm4t(uint32_t& r0, uint32_t& r1, uint32_t& r2, uint32_t& r3,
                                       uint32_t addr) {
    asm volatile("ldmatrix.sync.aligned.m8n8.x4.trans.shared.b16 {%0,%1,%2,%3}, [%4];"
                 : "=r"(r0), "=r"(r1), "=r"(r2), "=r"(r3) : "r"(addr));
}
__device__ __forceinline__ void mma16(float* d, const uint32_t* a, uint32_t b0, uint32_t b1) {
    asm volatile("mma.sync.aligned.m16n8k16.row.col.f32.f16.f16.f32 "
        "{%0,%1,%2,%3},{%4,%5,%6,%7},{%8,%9},{%0,%1,%2,%3};"
        : "+f"(d[0]), "+f"(d[1]), "+f"(d[2]), "+f"(d[3])
        : "r"(a[0]), "r"(a[1]), "r"(a[2]), "r"(a[3]), "r"(b0), "r"(b1));
}
__device__ __forceinline__ void cpa16(uint32_t dst, const void* src) {
    asm volatile("cp.async.cg.shared.global [%0], [%1], 16;" :: "r"(dst), "l"(src));
}
#define CP_COMMIT() asm volatile("cp.async.commit_group;" ::: "memory")
template <int NN> __device__ __forceinline__ void cp_wait() {
    asm volatile("cp.async.wait_group %0;" :: "n"(NN) : "memory");
}

// ---------------- prepass ----------------
#define WQ4   (512 * 512 / 4)
#define WKV4  (1024 * 2048 / 4)
#define WO4   (512 * 512 / 4)
__global__ __launch_bounds__(256)
void wcvt_kernel(const float* __restrict__ wq, const float* __restrict__ wkv,
                 const float* __restrict__ wout,
                 __half* __restrict__ dq, __half* __restrict__ dkv,
                 __half* __restrict__ dwo)
{
    const int i = blockIdx.x * 256 + threadIdx.x;
    const float* s;
    __half* d;
    int j;
    float sc;
    if (i < WQ4) {
        s = wq; d = dq; j = i; sc = 0.125f * 1.4426950408889634f;  // fold log2e
    } else if (i < WQ4 + WKV4) {
        s = wkv; d = dkv; j = i - WQ4; sc = 1.f;
    } else {
        s = wout; d = dwo; j = i - WQ4 - WKV4; sc = 1.f;
    }
    float4 v = reinterpret_cast<const float4*>(s)[j];
    reinterpret_cast<uint2*>(d)[j] =
        make_uint2(packh2(v.x * sc, v.y * sc), packh2(v.z * sc, v.w * sc));
}

// x [b][512][4096] f32 -> x^T [b][4096][512] half (64ch x 32pos tiles)
__global__ void trcvt_kernel(const float* __restrict__ S, __half* __restrict__ D)
{
    __shared__ float t2[32][65];
    const float* s = S + (size_t)blockIdx.z * DIM * HW;
    __half*      d = D + (size_t)blockIdx.z * HW * DIM;
    const int p0 = blockIdx.x * 32, c0 = blockIdx.y * 64;
    const int tx = threadIdx.x, ty = threadIdx.y;
#pragma unroll
    for (int j = 0; j < 64; j += 8)
        t2[tx][j + ty] = s[(size_t)(c0 + j + ty) * HW + p0 + tx];
    __syncthreads();
#pragma unroll
    for (int j = 0; j < 32; j += 8) {
        const int p = j + ty;
        *reinterpret_cast<uint32_t*>(d + (size_t)(p0 + p) * DIM + c0 + 2 * tx) =
            packh2(t2[p][2 * tx], t2[p][2 * tx + 1]);
    }
}

// im2col: x2[b][n][c*4 + p*2 + q] = x[b][c][(2i+p)*64 + 2j+q], n = 32i+j
__global__ __launch_bounds__(256)
void im2col_kernel(const float* __restrict__ X, __half* __restrict__ T)
{
    const int id = blockIdx.x * 256 + threadIdx.x;
    const int c = id & 511;
    const int n = (id >> 9) & 1023;
    const int b = id >> 19;
    const int i = n >> 5, j = n & 31;
    const float* xp = X + ((size_t)b * DIM + c) * HW + i * 128 + j * 2;
    float2 v0 = *reinterpret_cast<const float2*>(xp);
    float2 v1 = *reinterpret_cast<const float2*>(xp + 64);
    *reinterpret_cast<uint2*>(T + ((size_t)b * LKV + n) * 2048 + c * 4) =
        make_uint2(packh2(v0.x, v0.y), packh2(v1.x, v1.y));
}

// ---------------------------------------------------------------------------
// Unified all-half GEMM: C[b][m][n] = sum_k A[m][k] * B[b][n][k]
// 128 thr, 4 warps, warp tile 64x64, BK=32, 3-stage cp.async pipeline,
// ONE barrier per K-iteration (load issued after barrier -> no WAR race).
// Dynamic smem: 3 stages x (A 5120 + B 5120 halves) = 61,440 B.
// ---------------------------------------------------------------------------
#define GEMM_SMEM (3 * 2 * 128 * 40 * 2)

template <int M, int N, int K, bool OUTF32>
__global__ __launch_bounds__(128, 3)
void gemm_h(const __half* __restrict__ A, const __half* __restrict__ B, void* Cv)
{
    extern __shared__ __half smg[];
    const uint32_t asb = smem_u32(smg);            // A stages: +s*10240 B
    const uint32_t bsb = asb + 3 * 10240;          // B stages: +s*10240 B

    const int tid = threadIdx.x, lane = tid & 31, w = tid >> 5;
    const int g = lane >> 2, t = lane & 3;
    const int lr = lane & 7, lb3 = (lane >> 3) & 1, lb4 = (lane >> 4) & 1;
    const int m0w = (w >> 1) * 64, n0w = (w & 1) * 64;
    const int row0 = blockIdx.y * 128, col0 = blockIdx.x * 128;
    const int z = blockIdx.z;

    const __half* Bp = B + (size_t)z * N * K;

    auto LOAD = [&](int k0, int s) {
        const __half* ar = A  + (size_t)(row0 + tid) * K + k0;
        const __half* br = Bp + (size_t)(col0 + tid) * K + k0;
        const uint32_t ad = asb + s * 10240 + tid * 80;
        const uint32_t bd = bsb + s * 10240 + tid * 80;
#pragma unroll
        for (int u = 0; u < 4; u++) {
            cpa16(ad + u * 16, ar + u * 8);
            cpa16(bd + u * 16, br + u * 8);
        }
    };

    float acc[4][8][4];
#pragma unroll
    for (int mt = 0; mt < 4; mt++)
#pragma unroll
        for (int nt = 0; nt < 8; nt++)
#pragma unroll
            for (int r = 0; r < 4; r++) acc[mt][nt][r] = 0.f;

    constexpr int NIT = K / 32;
    LOAD(0, 0); CP_COMMIT();
    LOAD(32, 1); CP_COMMIT();

    for (int i = 0; i < NIT; i++) {
        const int buf = i % 3;
        if (i + 2 < NIT) cp_wait<1>(); else cp_wait<0>();
        __syncthreads();
        if (i + 2 < NIT) { LOAD((i + 2) * 32, (i + 2) % 3); CP_COMMIT(); }

        const uint32_t aB = asb + buf * 10240;
        const uint32_t bB = bsb + buf * 10240;
#pragma unroll
        for (int s = 0; s < 2; s++) {
            uint32_t a[4][4];
#pragma unroll
            for (int mt = 0; mt < 4; mt++)
                ldsm4(a[mt][0], a[mt][1], a[mt][2], a[mt][3],
                      aB + ((m0w + mt * 16 + lb3 * 8 + lr) * 40 + s * 16 + lb4 * 8) * 2);
            uint32_t b[8][2];
#pragma unroll
            for (int np = 0; np < 4; np++) {
                uint32_t r0, r1, r2, r3;
                ldsm4(r0, r1, r2, r3,
                      bB + ((n0w + np * 16 + lb3 * 8 + lr) * 40 + s * 16 + lb4 * 8) * 2);
                b[2 * np][0] = r0; b[2 * np][1] = r2;
                b[2 * np + 1][0] = r1; b[2 * np + 1][1] = r3;
            }
#pragma unroll
            for (int mt = 0; mt < 4; mt++)
#pragma unroll
                for (int nt = 0; nt < 8; nt++)
                    mma16(acc[mt][nt], a[mt], b[nt][0], b[nt][1]);
        }
    }

#pragma unroll
    for (int mt = 0; mt < 4; mt++)
#pragma unroll
        for (int nt = 0; nt < 8; nt++) {
            const int row = row0 + m0w + mt * 16 + g;
            const int col = col0 + n0w + nt * 8 + 2 * t;
            if (OUTF32) {
                float* Cp = (float*)Cv + (size_t)z * M * N;
                float2 v0; v0.x = acc[mt][nt][0]; v0.y = acc[mt][nt][1];
                float2 v1; v1.x = acc[mt][nt][2]; v1.y = acc[mt][nt][3];
                *reinterpret_cast<float2*>(Cp + (size_t)row * N + col)       = v0;
                *reinterpret_cast<float2*>(Cp + (size_t)(row + 8) * N + col) = v1;
            } else {
                __half* Cp = (__half*)Cv + (size_t)z * M * N;
                *reinterpret_cast<uint32_t*>(Cp + (size_t)row * N + col) =
                    packh2(acc[mt][nt][0], acc[mt][nt][1]);
                *reinterpret_cast<uint32_t*>(Cp + (size_t)(row + 8) * N + col) =
                    packh2(acc[mt][nt][2], acc[mt][nt][3]);
            }
        }
}

// ---------------------------------------------------------------------------
// fp16 flash attention, cp.async double-buffered K/V with ONE barrier per
// chunk (load issued after barrier), base-2 softmax, exp in f16x2.
// ---------------------------------------------------------------------------
#define ATTN_SMEM ((64 * 136 + 4 * 64 * 136) * 2)

__global__ __launch_bounds__(128, 2)
void attn_f16(const __half* __restrict__ Q, const __half* __restrict__ KV,
              __half* __restrict__ OT)
{
    const int bb = blockIdx.z, h = blockIdx.y, i0 = blockIdx.x * 128;
    const int tid = threadIdx.x, lane = tid & 31, w = tid >> 5;
    const int g = lane >> 2, t = lane & 3;
    const int lr = lane & 7, lb3 = (lane >> 3) & 1, lb4 = (lane >> 4) & 1;

    const __half* Qb = Q  + ((size_t)bb * DIM + h * DHEAD) * HW;
    const __half* Kb = KV + ((size_t)bb * 2 * DIM + h * DHEAD) * LKV;
    const __half* Vb = KV + ((size_t)bb * 2 * DIM + DIM + h * DHEAD) * LKV;

    extern __shared__ __half smh[];
    __half* Qs  = smh;
    __half* KV0 = Qs + 64 * 136;
    const uint32_t qb   = smem_u32(Qs);
    const uint32_t kvb0 = smem_u32(KV0);

#pragma unroll
    for (int it = 0; it < 8; it++) {
        const int d = (tid >> 4) + it * 8, col = (tid & 15) * 8;
        *reinterpret_cast<uint4*>(&Qs[d * 136 + col]) =
            *reinterpret_cast<const uint4*>(Qb + (size_t)d * HW + i0 + col);
    }

    auto LOADKV = [&](int j0, int buf) {
        const uint32_t base = kvb0 + buf * (2 * 64 * 136 * 2);
#pragma unroll
        for (int it = 0; it < 16; it++) {
            const int idx = tid + it * 128;
            const int sel = idx >> 10;
            const int r = (idx >> 4) & 63;
            const int c = idx & 15;
            const __half* src = (sel ? Vb : Kb) + (size_t)r * LKV + j0 + c * 8;
            cpa16(base + (sel * 64 * 136 + r * 136 + c * 8) * 2, src);
        }
    };

    float o[2][8][4];
#pragma unroll
    for (int mt = 0; mt < 2; mt++)
#pragma unroll
        for (int nt = 0; nt < 8; nt++)
#pragma unroll
            for (int r = 0; r < 4; r++) o[mt][nt][r] = 0.f;
    float mrow[4], lrow[4];
#pragma unroll
    for (int r = 0; r < 4; r++) { mrow[r] = -1e30f; lrow[r] = 0.f; }

    LOADKV(0, 0);
    CP_COMMIT();

    for (int jc = 0; jc < 8; jc++) {
        const int buf = jc & 1;
        cp_wait<0>();
        __syncthreads();
        if (jc + 1 < 8) { LOADKV((jc + 1) * 128, buf ^ 1); CP_COMMIT(); }

        const uint32_t kb = kvb0 + buf * (2 * 64 * 136 * 2);
        const uint32_t vb = kb + 64 * 136 * 2;

        float s[2][16][4];
#pragma unroll
        for (int mt = 0; mt < 2; mt++)
#pragma unroll
            for (int nt = 0; nt < 16; nt++)
#pragma unroll
                for (int r = 0; r < 4; r++) s[mt][nt][r] = 0.f;

#pragma unroll
        for (int ks = 0; ks < 4; ks++) {
            uint32_t a[2][4];
#pragma unroll
            for (int mt = 0; mt < 2; mt++)
                ldsm4t(a[mt][0], a[mt][1], a[mt][2], a[mt][3],
                       qb + ((16 * ks + lb4 * 8 + lr) * 136 + 32 * w + mt * 16 + lb3 * 8) * 2);
#pragma unroll
            for (int np = 0; np < 8; np++) {
                uint32_t b0, b1, b2, b3;
                ldsm4t(b0, b1, b2, b3,
                       kb + ((16 * ks + lb3 * 8 + lr) * 136 + np * 16 + lb4 * 8) * 2);
                mma16(s[0][2 * np],     a[0], b0, b1);
                mma16(s[0][2 * np + 1], a[0], b2, b3);
                mma16(s[1][2 * np],     a[1], b0, b1);
                mma16(s[1][2 * np + 1], a[1], b2, b3);
            }
        }

        // Online softmax, base 2; exp in f16x2 (result = phase-B A fragment)
        float fac[4];
#pragma unroll
        for (int mt = 0; mt < 2; mt++)
#pragma unroll
            for (int hh = 0; hh < 2; hh++) {
                const int idx = mt * 2 + hh;
                float mx = -1e30f;
#pragma unroll
                for (int nt = 0; nt < 16; nt++) {
                    mx = fmaxf(mx, s[mt][nt][2 * hh]);
                    mx = fmaxf(mx, s[mt][nt][2 * hh + 1]);
                }
                mx = fmaxf(mx, __shfl_xor_sync(0xffffffffu, mx, 1));
                mx = fmaxf(mx, __shfl_xor_sync(0xffffffffu, mx, 2));
                const float mn = fmaxf(mrow[idx], mx);
                fac[idx] = exp2f(mrow[idx] - mn);
                mrow[idx] = mn;
                float ls = 0.f;
#pragma unroll
                for (int nt = 0; nt < 16; nt++) {
                    uint32_t pp = packh2(s[mt][nt][2 * hh] - mn,
                                         s[mt][nt][2 * hh + 1] - mn);
                    asm("ex2.approx.f16x2 %0, %0;" : "+r"(pp));
                    s[mt][nt][2 * hh] = __uint_as_float(pp);
                    const __half2 hp = *reinterpret_cast<const __half2*>(&pp);
                    const float2 fp = __half22float2(hp);
                    ls += fp.x + fp.y;
                }
                lrow[idx] = lrow[idx] * fac[idx] + ls;
            }

#pragma unroll
        for (int mt = 0; mt < 2; mt++)
#pragma unroll
            for (int nt = 0; nt < 8; nt++) {
                o[mt][nt][0] *= fac[mt * 2];
                o[mt][nt][1] *= fac[mt * 2];
                o[mt][nt][2] *= fac[mt * 2 + 1];
                o[mt][nt][3] *= fac[mt * 2 + 1];
            }

#pragma unroll
        for (int ks = 0; ks < 8; ks++) {
            uint32_t pa[2][4];
#pragma unroll
            for (int mt = 0; mt < 2; mt++) {
                pa[mt][0] = __float_as_uint(s[mt][2 * ks][0]);
                pa[mt][1] = __float_as_uint(s[mt][2 * ks][2]);
                pa[mt][2] = __float_as_uint(s[mt][2 * ks + 1][0]);
                pa[mt][3] = __float_as_uint(s[mt][2 * ks + 1][2]);
            }
#pragma unroll
            for (int np = 0; np < 4; np++) {
                uint32_t b0, b1, b2, b3;
                ldsm4(b0, b1, b2, b3,
                      vb + ((16 * np + lb4 * 8 + lr) * 136 + 16 * ks + lb3 * 8) * 2);
                mma16(o[0][2 * np],     pa[0], b0, b1);
                mma16(o[0][2 * np + 1], pa[0], b2, b3);
                mma16(o[1][2 * np],     pa[1], b0, b1);
                mma16(o[1][2 * np + 1], pa[1], b2, b3);
            }
        }
    }

    float inv[4];
#pragma unroll
    for (int idx = 0; idx < 4; idx++) {
        float ls = lrow[idx];
        ls += __shfl_xor_sync(0xffffffffu, ls, 1);
        ls += __shfl_xor_sync(0xffffffffu, ls, 2);
        inv[idx] = 1.f / ls;
    }

    __syncthreads();
    __half* Of = KV0;
#pragma unroll
    for (int mt = 0; mt < 2; mt++) {
        const int row = 32 * w + mt * 16 + g;
#pragma unroll
        for (int nt = 0; nt < 8; nt++) {
            const int d = nt * 8 + 2 * t;
            Of[row * 72 + d]           = __float2half(o[mt][nt][0] * inv[mt * 2]);
            Of[row * 72 + d + 1]       = __float2half(o[mt][nt][1] * inv[mt * 2]);
            Of[(row + 8) * 72 + d]     = __float2half(o[mt][nt][2] * inv[mt * 2 + 1]);
            Of[(row + 8) * 72 + d + 1] = __float2half(o[mt][nt][3] * inv[mt * 2 + 1]);
        }
    }
    __syncthreads();

    __half* dst = OT + ((size_t)bb * HW + i0 + tid) * DIM + h * DHEAD;
#pragma unroll
    for (int u = 0; u < 8; u++)
        reinterpret_cast<uint4*>(dst)[u] =
            *reinterpret_cast<const uint4*>(Of + tid * 72 + u * 8);
}

// ---------------- launch (single stream) ----------------
extern "C" void kernel_launch(void* const* d_in, const int* in_sizes, int n_in,
                              void* d_out, int out_size)
{
    const float* x    = (const float*)d_in[0];
    const float* wq   = (const float*)d_in[1];
    const float* wkv  = (const float*)d_in[2];
    const float* wout = (const float*)d_in[3];
    float* out = (float*)d_out;

    __half *wqh, *wkvh, *woh, *xt, *x2, *qh, *kvh, *ot;
    cudaGetSymbolAddress((void**)&wqh,  g_wq);
    cudaGetSymbolAddress((void**)&wkvh, g_wkv);
    cudaGetSymbolAddress((void**)&woh,  g_wo);
    cudaGetSymbolAddress((void**)&xt,   g_xt);
    cudaGetSymbolAddress((void**)&x2,   g_x2);
    cudaGetSymbolAddress((void**)&qh,   g_q);
    cudaGetSymbolAddress((void**)&kvh,  g_kv);
    cudaGetSymbolAddress((void**)&ot,   g_ot);

    cudaFuncSetAttribute(attn_f16,
                         cudaFuncAttributeMaxDynamicSharedMemorySize, ATTN_SMEM);
    cudaFuncSetAttribute(gemm_h<512, 4096, 512, false>,
                         cudaFuncAttributeMaxDynamicSharedMemorySize, GEMM_SMEM);
    cudaFuncSetAttribute(gemm_h<1024, 1024, 2048, false>,
                         cudaFuncAttributeMaxDynamicSharedMemorySize, GEMM_SMEM);
    cudaFuncSetAttribute(gemm_h<512, 4096, 512, true>,
                         cudaFuncAttributeMaxDynamicSharedMemorySize, GEMM_SMEM);

    // prepass (merged weight cvt; log2e*0.125 folded into wq)
    wcvt_kernel<<<(WQ4 + WKV4 + WO4 + 255) / 256, 256>>>(wq, wkv, wout, wqh, wkvh, woh);
    trcvt_kernel<<<dim3(128, 8, BATCH), dim3(32, 8)>>>(x, xt);
    im2col_kernel<<<BATCH * LKV * 512 / 256, 256>>>(x, x2);

    // Q = (0.125*log2e * wq) @ x : [ch][pos] half
    gemm_h<512, 4096, 512, false><<<dim3(32, 4, BATCH), 128, GEMM_SMEM>>>(wqh, xt, qh);
    // KV = wkv @ im2col(x) : [och][ij] half
    gemm_h<1024, 1024, 2048, false><<<dim3(8, 8, BATCH), 128, GEMM_SMEM>>>(wkvh, x2, kvh);
    // attention -> O^T [pos][ch] half
    attn_f16<<<dim3(HW / 128, HEADS, BATCH), 128, ATTN_SMEM>>>(qh, kvh, ot);
    // Y = wout @ O : fp32 out
    gemm_h<512, 4096, 512, true><<<dim3(32, 4, BATCH), 128, GEMM_SMEM>>>(woh, ot, out);
}

// round 14
// speedup vs baseline: 1.0772x; 1.0772x over previous
#include <cuda_runtime.h>
#include <cuda_fp16.h>
#include <cstdint>

#define BATCH 4
#define DIM   512
#define HEADS 8
#define DHEAD 64
#define HW    4096
#define LKV   1024

// fp16 scratch (device globals; allocation-free)
__device__ __half g_wq [512 * 512];
__device__ __half g_wkv[1024 * 2048];   // k-reordered: k' = pq*512 + c
__device__ __half g_wo [512 * 512];
__device__ __half g_xt [BATCH * HW * DIM];     // x^T    [b][pos][ch]
__device__ __half g_q  [BATCH * DIM * HW];     // Q      [b][ch][pos]
__device__ __half g_kv [BATCH * 2 * DIM * LKV];// KV     [b][och][ij]
__device__ __half g_ot [BATCH * HW * DIM];     // attnO^T[b][pos][ch]

// ---------------- helpers ----------------
__device__ __forceinline__ uint32_t packh2(float lo, float hi) {
    uint32_t r;
    asm("cvt.rn.f16x2.f32 %0, %1, %2;" : "=r"(r) : "f"(hi), "f"(lo));
    return r;
}
__device__ __forceinline__ uint32_t smem_u32(const void* p) {
    uint32_t a;
    asm("{ .reg .u64 t; cvta.to.shared.u64 t, %1; cvt.u32.u64 %0, t; }" : "=r"(a) : "l"(p));
    return a;
}
__device__ __forceinline__ void ldsm4(uint32_t& r0, uint32_t& r1, uint32_t& r2, uint32_t& r3,
                                      uint32_t addr) {
    asm volatile("ldmatrix.sync.aligned.m8n8.x4.shared.b16 {%0,%1,%2,%3}, [%4];"
                 : "=r"(r0), "=r"(r1), "=r"(r2), "=r"(r3) : "r"(addr));
}
__device__ __forceinline__ void ldsm4t(uint32_t& r0, uint32_t& r1, uint32_t& r2, uint32_t& r3,
                                       uint32_t addr) {
    asm volatile("ldmatrix.sync.aligned.m8n8.x4.trans.shared.b16 {%0,%1,%2,%3}, [%4];"
                 : "=r"(r0), "=r"(r1), "=r"(r2), "=r"(r3) : "r"(addr));
}
__device__ __forceinline__ void mma16(float* d, const uint32_t* a, uint32_t b0, uint32_t b1) {
    asm volatile("mma.sync.aligned.m16n8k16.row.col.f32.f16.f16.f32 "
        "{%0,%1,%2,%3},{%4,%5,%6,%7},{%8,%9},{%0,%1,%2,%3};"
        : "+f"(d[0]), "+f"(d[1]), "+f"(d[2]), "+f"(d[3])
        : "r"(a[0]), "r"(a[1]), "r"(a[2]), "r"(a[3]), "r"(b0), "r"(b1));
}
__device__ __forceinline__ void cpa16(uint32_t dst, const void* src) {
    asm volatile("cp.async.cg.shared.global [%0], [%1], 16;" :: "r"(dst), "l"(src));
}
#define CP_COMMIT() asm volatile("cp.async.commit_group;" ::: "memory")
template <int NN> __device__ __forceinline__ void cp_wait() {
    asm volatile("cp.async.wait_group %0;" :: "n"(NN) : "memory");
}

// ---------------- prepass ----------------
// Merged weight conversion. wq gets 0.125*log2e folded. wkv is k-REORDERED:
// dst k' = pq*512 + c  <=  src k = c*4 + pq   (permutation; dot products
// unchanged because the kv-GEMM B operand is built in the same k' order).
#define WQ4   (512 * 512 / 4)
#define WKV4  (1024 * 2048 / 4)
#define WO4   (512 * 512 / 4)
__global__ __launch_bounds__(256)
void wcvt_kernel(const float* __restrict__ wq, const float* __restrict__ wkv,
                 const float* __restrict__ wout,
                 __half* __restrict__ dq, __half* __restrict__ dkv,
                 __half* __restrict__ dwo)
{
    const int i = blockIdx.x * 256 + threadIdx.x;
    if (i < WQ4) {
        const float sc = 0.125f * 1.4426950408889634f;
        float4 v = reinterpret_cast<const float4*>(wq)[i];
        reinterpret_cast<uint2*>(dq)[i] =
            make_uint2(packh2(v.x * sc, v.y * sc), packh2(v.z * sc, v.w * sc));
    } else if (i < WQ4 + WKV4) {
        const int j = i - WQ4;          // src granule: m row, c = j & 511
        const int m = j >> 9, c = j & 511;
        float4 v = reinterpret_cast<const float4*>(wkv)[j];
        __half* drow = dkv + (size_t)m * 2048 + c;
        drow[0]        = __float2half_rn(v.x);   // pq=0
        drow[512]      = __float2half_rn(v.y);   // pq=1
        drow[1024]     = __float2half_rn(v.z);   // pq=2
        drow[1536]     = __float2half_rn(v.w);   // pq=3
    } else {
        const int j = i - WQ4 - WKV4;
        float4 v = reinterpret_cast<const float4*>(wout)[j];
        reinterpret_cast<uint2*>(dwo)[j] =
            make_uint2(packh2(v.x, v.y), packh2(v.z, v.w));
    }
}

// x [b][512][4096] f32 -> x^T [b][4096][512] half (64ch x 32pos tiles)
__global__ void trcvt_kernel(const float* __restrict__ S, __half* __restrict__ D)
{
    __shared__ float t2[32][65];
    const float* s = S + (size_t)blockIdx.z * DIM * HW;
    __half*      d = D + (size_t)blockIdx.z * HW * DIM;
    const int p0 = blockIdx.x * 32, c0 = blockIdx.y * 64;
    const int tx = threadIdx.x, ty = threadIdx.y;
#pragma unroll
    for (int j = 0; j < 64; j += 8)
        t2[tx][j + ty] = s[(size_t)(c0 + j + ty) * HW + p0 + tx];
    __syncthreads();
#pragma unroll
    for (int j = 0; j < 32; j += 8) {
        const int p = j + ty;
        *reinterpret_cast<uint32_t*>(d + (size_t)(p0 + p) * DIM + c0 + 2 * tx) =
            packh2(t2[p][2 * tx], t2[p][2 * tx + 1]);
    }
}

// ---------------------------------------------------------------------------
// Unified all-half GEMM: C[b][m][n] = sum_k A[m][k] * B'[b][n][k]
// BMODE 0: B is a plain [n][k] half matrix (batch stride N*K).
// BMODE 1: B rows are gathered from x^T (implicit im2col, k' = pq*512+c):
//          B[n][pq*512+c] = xt[(2i+p)*64+2j+q][c], n = 32i+j.
// 128 thr, 4 warps, warp tile 64x64, BK=32, 3-stage cp.async pipeline,
// ONE barrier per K-iteration (loads issued after the barrier).
// ---------------------------------------------------------------------------
#define GEMM_SMEM (3 * 2 * 128 * 40 * 2)

template <int M, int N, int K, bool OUTF32, int BMODE>
__global__ __launch_bounds__(128, 3)
void gemm_h(const __half* __restrict__ A, const __half* __restrict__ B, void* Cv)
{
    extern __shared__ __half smg[];
    const uint32_t asb = smem_u32(smg);            // A stages: +s*10240 B
    const uint32_t bsb = asb + 3 * 10240;          // B stages: +s*10240 B

    const int tid = threadIdx.x, lane = tid & 31, w = tid >> 5;
    const int g = lane >> 2, t = lane & 3;
    const int lr = lane & 7, lb3 = (lane >> 3) & 1, lb4 = (lane >> 4) & 1;
    const int m0w = (w >> 1) * 64, n0w = (w & 1) * 64;
    const int row0 = blockIdx.y * 128, col0 = blockIdx.x * 128;
    const int z = blockIdx.z;

    const __half* Bp = B + (size_t)z * N * K;   // (for BMODE1: xt batch, HW*512 == N*K)

    auto LOAD = [&](int k0, int s) {
        const __half* ar = A + (size_t)(row0 + tid) * K + k0;
        const __half* br;
        if (BMODE == 1) {
            const int n  = col0 + tid;
            const int pq = k0 >> 9;
            const int pos = (2 * (n >> 5) + (pq >> 1)) * 64 + 2 * (n & 31) + (pq & 1);
            br = Bp + (size_t)pos * 512 + (k0 & 511);
        } else {
            br = Bp + (size_t)(col0 + tid) * K + k0;
        }
        const uint32_t ad = asb + s * 10240 + tid * 80;
        const uint32_t bd = bsb + s * 10240 + tid * 80;
#pragma unroll
        for (int u = 0; u < 4; u++) {
            cpa16(ad + u * 16, ar + u * 8);
            cpa16(bd + u * 16, br + u * 8);
        }
    };

    float acc[4][8][4];
#pragma unroll
    for (int mt = 0; mt < 4; mt++)
#pragma unroll
        for (int nt = 0; nt < 8; nt++)
#pragma unroll
            for (int r = 0; r < 4; r++) acc[mt][nt][r] = 0.f;

    constexpr int NIT = K / 32;
    LOAD(0, 0); CP_COMMIT();
    LOAD(32, 1); CP_COMMIT();

    for (int i = 0; i < NIT; i++) {
        const int buf = i % 3;
        if (i + 2 < NIT) cp_wait<1>(); else cp_wait<0>();
        __syncthreads();
        if (i + 2 < NIT) { LOAD((i + 2) * 32, (i + 2) % 3); CP_COMMIT(); }

        const uint32_t aB = asb + buf * 10240;
        const uint32_t bB = bsb + buf * 10240;
#pragma unroll
        for (int s = 0; s < 2; s++) {
            uint32_t a[4][4];
#pragma unroll
            for (int mt = 0; mt < 4; mt++)
                ldsm4(a[mt][0], a[mt][1], a[mt][2], a[mt][3],
                      aB + ((m0w + mt * 16 + lb3 * 8 + lr) * 40 + s * 16 + lb4 * 8) * 2);
            uint32_t b[8][2];
#pragma unroll
            for (int np = 0; np < 4; np++) {
                uint32_t r0, r1, r2, r3;
                ldsm4(r0, r1, r2, r3,
                      bB + ((n0w + np * 16 + lb3 * 8 + lr) * 40 + s * 16 + lb4 * 8) * 2);
                b[2 * np][0] = r0; b[2 * np][1] = r2;
                b[2 * np + 1][0] = r1; b[2 * np + 1][1] = r3;
            }
#pragma unroll
            for (int mt = 0; mt < 4; mt++)
#pragma unroll
                for (int nt = 0; nt < 8; nt++)
                    mma16(acc[mt][nt], a[mt], b[nt][0], b[nt][1]);
        }
    }

#pragma unroll
    for (int mt = 0; mt < 4; mt++)
#pragma unroll
        for (int nt = 0; nt < 8; nt++) {
            const int row = row0 + m0w + mt * 16 + g;
            const int col = col0 + n0w + nt * 8 + 2 * t;
            if (OUTF32) {
                float* Cp = (float*)Cv + (size_t)z * M * N;
                float2 v0; v0.x = acc[mt][nt][0]; v0.y = acc[mt][nt][1];
                float2 v1; v1.x = acc[mt][nt][2]; v1.y = acc[mt][nt][3];
                *reinterpret_cast<float2*>(Cp + (size_t)row * N + col)       = v0;
                *reinterpret_cast<float2*>(Cp + (size_t)(row + 8) * N + col) = v1;
            } else {
                __half* Cp = (__half*)Cv + (size_t)z * M * N;
                *reinterpret_cast<uint32_t*>(Cp + (size_t)row * N + col) =
                    packh2(acc[mt][nt][0], acc[mt][nt][1]);
                *reinterpret_cast<uint32_t*>(Cp + (size_t)(row + 8) * N + col) =
                    packh2(acc[mt][nt][2], acc[mt][nt][3]);
            }
        }
}

// ---------------------------------------------------------------------------
// fp16 flash attention, cp.async double-buffered K/V (race-free single-barrier
// ordering), Q loaded via cp.async in the first group, base-2 softmax with
// exp in f16x2.
// ---------------------------------------------------------------------------
#define ATTN_SMEM ((64 * 136 + 4 * 64 * 136) * 2)

__global__ __launch_bounds__(128, 2)
void attn_f16(const __half* __restrict__ Q, const __half* __restrict__ KV,
              __half* __restrict__ OT)
{
    const int bb = blockIdx.z, h = blockIdx.y, i0 = blockIdx.x * 128;
    const int tid = threadIdx.x, lane = tid & 31, w = tid >> 5;
    const int g = lane >> 2, t = lane & 3;
    const int lr = lane & 7, lb3 = (lane >> 3) & 1, lb4 = (lane >> 4) & 1;

    const __half* Qb = Q  + ((size_t)bb * DIM + h * DHEAD) * HW;
    const __half* Kb = KV + ((size_t)bb * 2 * DIM + h * DHEAD) * LKV;
    const __half* Vb = KV + ((size_t)bb * 2 * DIM + DIM + h * DHEAD) * LKV;

    extern __shared__ __half smh[];
    __half* Qs  = smh;
    __half* KV0 = Qs + 64 * 136;
    const uint32_t qb   = smem_u32(Qs);
    const uint32_t kvb0 = smem_u32(KV0);

    auto LOADKV = [&](int j0, int buf) {
        const uint32_t base = kvb0 + buf * (2 * 64 * 136 * 2);
#pragma unroll
        for (int it = 0; it < 16; it++) {
            const int idx = tid + it * 128;
            const int sel = idx >> 10;
            const int r = (idx >> 4) & 63;
            const int c = idx & 15;
            const __half* src = (sel ? Vb : Kb) + (size_t)r * LKV + j0 + c * 8;
            cpa16(base + (sel * 64 * 136 + r * 136 + c * 8) * 2, src);
        }
    };

    // Q tile + first KV chunk in one cp.async group
#pragma unroll
    for (int it = 0; it < 8; it++) {
        const int d = (tid >> 4) + it * 8, col = (tid & 15) * 8;
        cpa16(qb + (d * 136 + col) * 2, Qb + (size_t)d * HW + i0 + col);
    }
    LOADKV(0, 0);
    CP_COMMIT();

    float o[2][8][4];
#pragma unroll
    for (int mt = 0; mt < 2; mt++)
#pragma unroll
        for (int nt = 0; nt < 8; nt++)
#pragma unroll
            for (int r = 0; r < 4; r++) o[mt][nt][r] = 0.f;
    float mrow[4], lrow[4];
#pragma unroll
    for (int r = 0; r < 4; r++) { mrow[r] = -1e30f; lrow[r] = 0.f; }

    for (int jc = 0; jc < 8; jc++) {
        const int buf = jc & 1;
        cp_wait<0>();
        __syncthreads();
        if (jc + 1 < 8) { LOADKV((jc + 1) * 128, buf ^ 1); CP_COMMIT(); }

        const uint32_t kb = kvb0 + buf * (2 * 64 * 136 * 2);
        const uint32_t vb = kb + 64 * 136 * 2;

        float s[2][16][4];
#pragma unroll
        for (int mt = 0; mt < 2; mt++)
#pragma unroll
            for (int nt = 0; nt < 16; nt++)
#pragma unroll
                for (int r = 0; r < 4; r++) s[mt][nt][r] = 0.f;

#pragma unroll
        for (int ks = 0; ks < 4; ks++) {
            uint32_t a[2][4];
#pragma unroll
            for (int mt = 0; mt < 2; mt++)
                ldsm4t(a[mt][0], a[mt][1], a[mt][2], a[mt][3],
                       qb + ((16 * ks + lb4 * 8 + lr) * 136 + 32 * w + mt * 16 + lb3 * 8) * 2);
#pragma unroll
            for (int np = 0; np < 8; np++) {
                uint32_t b0, b1, b2, b3;
                ldsm4t(b0, b1, b2, b3,
                       kb + ((16 * ks + lb3 * 8 + lr) * 136 + np * 16 + lb4 * 8) * 2);
                mma16(s[0][2 * np],     a[0], b0, b1);
                mma16(s[0][2 * np + 1], a[0], b2, b3);
                mma16(s[1][2 * np],     a[1], b0, b1);
                mma16(s[1][2 * np + 1], a[1], b2, b3);
            }
        }

        // Online softmax, base 2; exp in f16x2 (result = phase-B A fragment)
        float fac[4];
#pragma unroll
        for (int mt = 0; mt < 2; mt++)
#pragma unroll
            for (int hh = 0; hh < 2; hh++) {
                const int idx = mt * 2 + hh;
                float mx = -1e30f;
#pragma unroll
                for (int nt = 0; nt < 16; nt++) {
                    mx = fmaxf(mx, s[mt][nt][2 * hh]);
                    mx = fmaxf(mx, s[mt][nt][2 * hh + 1]);
                }
                mx = fmaxf(mx, __shfl_xor_sync(0xffffffffu, mx, 1));
                mx = fmaxf(mx, __shfl_xor_sync(0xffffffffu, mx, 2));
                const float mn = fmaxf(mrow[idx], mx);
                fac[idx] = exp2f(mrow[idx] - mn);
                mrow[idx] = mn;
                float ls = 0.f;
#pragma unroll
                for (int nt = 0; nt < 16; nt++) {
                    uint32_t pp = packh2(s[mt][nt][2 * hh] - mn,
                                         s[mt][nt][2 * hh + 1] - mn);
                    asm("ex2.approx.f16x2 %0, %0;" : "+r"(pp));
                    s[mt][nt][2 * hh] = __uint_as_float(pp);
                    const __half2 hp = *reinterpret_cast<const __half2*>(&pp);
                    const float2 fp = __half22float2(hp);
                    ls += fp.x + fp.y;
                }
                lrow[idx] = lrow[idx] * fac[idx] + ls;
            }

#pragma unroll
        for (int mt = 0; mt < 2; mt++)
#pragma unroll
            for (int nt = 0; nt < 8; nt++) {
                o[mt][nt][0] *= fac[mt * 2];
                o[mt][nt][1] *= fac[mt * 2];
                o[mt][nt][2] *= fac[mt * 2 + 1];
                o[mt][nt][3] *= fac[mt * 2 + 1];
            }

#pragma unroll
        for (int ks = 0; ks < 8; ks++) {
            uint32_t pa[2][4];
#pragma unroll
            for (int mt = 0; mt < 2; mt++) {
                pa[mt][0] = __float_as_uint(s[mt][2 * ks][0]);
                pa[mt][1] = __float_as_uint(s[mt][2 * ks][2]);
                pa[mt][2] = __float_as_uint(s[mt][2 * ks + 1][0]);
                pa[mt][3] = __float_as_uint(s[mt][2 * ks + 1][2]);
            }
#pragma unroll
            for (int np = 0; np < 4; np++) {
                uint32_t b0, b1, b2, b3;
                ldsm4(b0, b1, b2, b3,
                      vb + ((16 * np + lb4 * 8 + lr) * 136 + 16 * ks + lb3 * 8) * 2);
                mma16(o[0][2 * np],     pa[0], b0, b1);
                mma16(o[0][2 * np + 1], pa[0], b2, b3);
                mma16(o[1][2 * np],     pa[1], b0, b1);
                mma16(o[1][2 * np + 1], pa[1], b2, b3);
            }
        }
    }

    float inv[4];
#pragma unroll
    for (int idx = 0; idx < 4; idx++) {
        float ls = lrow[idx];
        ls += __shfl_xor_sync(0xffffffffu, ls, 1);
        ls += __shfl_xor_sync(0xffffffffu, ls, 2);
        inv[idx] = 1.f / ls;
    }

    __syncthreads();
    __half* Of = KV0;
#pragma unroll
    for (int mt = 0; mt < 2; mt++) {
        const int row = 32 * w + mt * 16 + g;
#pragma unroll
        for (int nt = 0; nt < 8; nt++) {
            const int d = nt * 8 + 2 * t;
            Of[row * 72 + d]           = __float2half(o[mt][nt][0] * inv[mt * 2]);
            Of[row * 72 + d + 1]       = __float2half(o[mt][nt][1] * inv[mt * 2]);
            Of[(row + 8) * 72 + d]     = __float2half(o[mt][nt][2] * inv[mt * 2 + 1]);
            Of[(row + 8) * 72 + d + 1] = __float2half(o[mt][nt][3] * inv[mt * 2 + 1]);
        }
    }
    __syncthreads();

    __half* dst = OT + ((size_t)bb * HW + i0 + tid) * DIM + h * DHEAD;
#pragma unroll
    for (int u = 0; u < 8; u++)
        reinterpret_cast<uint4*>(dst)[u] =
            *reinterpret_cast<const uint4*>(Of + tid * 72 + u * 8);
}

// ---------------- launch (single stream) ----------------
extern "C" void kernel_launch(void* const* d_in, const int* in_sizes, int n_in,
                              void* d_out, int out_size)
{
    const float* x    = (const float*)d_in[0];
    const float* wq   = (const float*)d_in[1];
    const float* wkv  = (const float*)d_in[2];
    const float* wout = (const float*)d_in[3];
    float* out = (float*)d_out;

    __half *wqh, *wkvh, *woh, *xt, *qh, *kvh, *ot;
    cudaGetSymbolAddress((void**)&wqh,  g_wq);
    cudaGetSymbolAddress((void**)&wkvh, g_wkv);
    cudaGetSymbolAddress((void**)&woh,  g_wo);
    cudaGetSymbolAddress((void**)&xt,   g_xt);
    cudaGetSymbolAddress((void**)&qh,   g_q);
    cudaGetSymbolAddress((void**)&kvh,  g_kv);
    cudaGetSymbolAddress((void**)&ot,   g_ot);

    cudaFuncSetAttribute(attn_f16,
                         cudaFuncAttributeMaxDynamicSharedMemorySize, ATTN_SMEM);
    cudaFuncSetAttribute(gemm_h<512, 4096, 512, false, 0>,
                         cudaFuncAttributeMaxDynamicSharedMemorySize, GEMM_SMEM);
    cudaFuncSetAttribute(gemm_h<1024, 1024, 2048, false, 1>,
                         cudaFuncAttributeMaxDynamicSharedMemorySize, GEMM_SMEM);
    cudaFuncSetAttribute(gemm_h<512, 4096, 512, true, 0>,
                         cudaFuncAttributeMaxDynamicSharedMemorySize, GEMM_SMEM);

    // prepass: weights (wq scaled, wkv k-reordered) + x^T
    wcvt_kernel<<<(WQ4 + WKV4 + WO4 + 255) / 256, 256>>>(wq, wkv, wout, wqh, wkvh, woh);
    trcvt_kernel<<<dim3(128, 8, BATCH), dim3(32, 8)>>>(x, xt);

    // Q = (0.125*log2e * wq) @ x : [ch][pos] half
    gemm_h<512, 4096, 512, false, 0><<<dim3(32, 4, BATCH), 128, GEMM_SMEM>>>(wqh, xt, qh);
    // KV = wkv' @ im2col(x) — B gathered directly from x^T (no im2col pass)
    gemm_h<1024, 1024, 2048, false, 1><<<dim3(8, 8, BATCH), 128, GEMM_SMEM>>>(wkvh, xt, kvh);
    // attention -> O^T [pos][ch] half
    attn_f16<<<dim3(HW / 128, HEADS, BATCH), 128, ATTN_SMEM>>>(qh, kvh, ot);
    // Y = wout @ O : fp32 out
    gemm_h<512, 4096, 512, true, 0><<<dim3(32, 4, BATCH), 128, GEMM_SMEM>>>(woh, ot, out);
}

// round 15
// speedup vs baseline: 1.1446x; 1.0626x over previous
#include <cuda_runtime.h>
#include <cuda_fp16.h>
#include <cstdint>

#define BATCH 4
#define DIM   512
#define HEADS 8
#define DHEAD 64
#define HW    4096
#define LKV   1024

// fp16 scratch (device globals; allocation-free)
__device__ __half g_wq [512 * 512];
__device__ __half g_wkv[1024 * 2048];   // k-reordered: k' = pq*512 + c
__device__ __half g_wo [512 * 512];
__device__ __half g_xt [BATCH * HW * DIM];     // x^T    [b][pos][ch]
__device__ __half g_q  [BATCH * DIM * HW];     // Q      [b][ch][pos]
__device__ __half g_kv [BATCH * 2 * DIM * LKV];// KV     [b][och][ij]
__device__ __half g_ot [BATCH * HW * DIM];     // attnO^T[b][pos][ch]

// ---------------- helpers ----------------
__device__ __forceinline__ uint32_t packh2(float lo, float hi) {
    uint32_t r;
    asm("cvt.rn.f16x2.f32 %0, %1, %2;" : "=r"(r) : "f"(hi), "f"(lo));
    return r;
}
__device__ __forceinline__ uint32_t smem_u32(const void* p) {
    uint32_t a;
    asm("{ .reg .u64 t; cvta.to.shared.u64 t, %1; cvt.u32.u64 %0, t; }" : "=r"(a) : "l"(p));
    return a;
}
__device__ __forceinline__ void ldsm4(uint32_t& r0, uint32_t& r1, uint32_t& r2, uint32_t& r3,
                                      uint32_t addr) {
    asm volatile("ldmatrix.sync.aligned.m8n8.x4.shared.b16 {%0,%1,%2,%3}, [%4];"
                 : "=r"(r0), "=r"(r1), "=r"(r2), "=r"(r3) : "r"(addr));
}
__device__ __forceinline__ void ldsm4t(uint32_t& r0, uint32_t& r1, uint32_t& r2, uint32_t& r3,
                                       uint32_t addr) {
    asm volatile("ldmatrix.sync.aligned.m8n8.x4.trans.shared.b16 {%0,%1,%2,%3}, [%4];"
                 : "=r"(r0), "=r"(r1), "=r"(r2), "=r"(r3) : "r"(addr));
}
__device__ __forceinline__ void mma16(float* d, const uint32_t* a, uint32_t b0, uint32_t b1) {
    asm volatile("mma.sync.aligned.m16n8k16.row.col.f32.f16.f16.f32 "
        "{%0,%1,%2,%3},{%4,%5,%6,%7},{%8,%9},{%0,%1,%2,%3};"
        : "+f"(d[0]), "+f"(d[1]), "+f"(d[2]), "+f"(d[3])
        : "r"(a[0]), "r"(a[1]), "r"(a[2]), "r"(a[3]), "r"(b0), "r"(b1));
}
__device__ __forceinline__ void cpa16(uint32_t dst, const void* src) {
    asm volatile("cp.async.cg.shared.global [%0], [%1], 16;" :: "r"(dst), "l"(src));
}
#define CP_COMMIT() asm volatile("cp.async.commit_group;" ::: "memory")
template <int NN> __device__ __forceinline__ void cp_wait() {
    asm volatile("cp.async.wait_group %0;" :: "n"(NN) : "memory");
}

// ---------------- prepass ----------------
// Merged weight conversion. wq gets 0.125*log2e folded. wkv is k-REORDERED:
// dst k' = pq*512 + c  <=  src k = c*4 + pq.
#define WQ4   (512 * 512 / 4)
#define WKV4  (1024 * 2048 / 4)
#define WO4   (512 * 512 / 4)
__global__ __launch_bounds__(256)
void wcvt_kernel(const float* __restrict__ wq, const float* __restrict__ wkv,
                 const float* __restrict__ wout,
                 __half* __restrict__ dq, __half* __restrict__ dkv,
                 __half* __restrict__ dwo)
{
    const int i = blockIdx.x * 256 + threadIdx.x;
    if (i < WQ4) {
        const float sc = 0.125f * 1.4426950408889634f;
        float4 v = reinterpret_cast<const float4*>(wq)[i];
        reinterpret_cast<uint2*>(dq)[i] =
            make_uint2(packh2(v.x * sc, v.y * sc), packh2(v.z * sc, v.w * sc));
    } else if (i < WQ4 + WKV4) {
        const int j = i - WQ4;
        const int m = j >> 9, c = j & 511;
        float4 v = reinterpret_cast<const float4*>(wkv)[j];
        __half* drow = dkv + (size_t)m * 2048 + c;
        drow[0]    = __float2half_rn(v.x);   // pq=0
        drow[512]  = __float2half_rn(v.y);   // pq=1
        drow[1024] = __float2half_rn(v.z);   // pq=2
        drow[1536] = __float2half_rn(v.w);   // pq=3
    } else {
        const int j = i - WQ4 - WKV4;
        float4 v = reinterpret_cast<const float4*>(wout)[j];
        reinterpret_cast<uint2*>(dwo)[j] =
            make_uint2(packh2(v.x, v.y), packh2(v.z, v.w));
    }
}

// x [b][512][4096] f32 -> x^T [b][4096][512] half (64ch x 32pos tiles)
__global__ void trcvt_kernel(const float* __restrict__ S, __half* __restrict__ D)
{
    __shared__ float t2[32][65];
    const float* s = S + (size_t)blockIdx.z * DIM * HW;
    __half*      d = D + (size_t)blockIdx.z * HW * DIM;
    const int p0 = blockIdx.x * 32, c0 = blockIdx.y * 64;
    const int tx = threadIdx.x, ty = threadIdx.y;
#pragma unroll
    for (int j = 0; j < 64; j += 8)
        t2[tx][j + ty] = s[(size_t)(c0 + j + ty) * HW + p0 + tx];
    __syncthreads();
#pragma unroll
    for (int j = 0; j < 32; j += 8) {
        const int p = j + ty;
        *reinterpret_cast<uint32_t*>(d + (size_t)(p0 + p) * DIM + c0 + 2 * tx) =
            packh2(t2[p][2 * tx], t2[p][2 * tx + 1]);
    }
}

// ---------------------------------------------------------------------------
// All-half GEMM (128 threads, 4 warps, warp tile 64x64) — q/out GEMMs.
// BMODE 0: plain [n][k]. BMODE 1: implicit im2col from x^T (k' = pq*512+c).
// 3-stage cp.async pipeline, ONE barrier per K-iteration.
// ---------------------------------------------------------------------------
#define GEMM_SMEM (3 * 2 * 128 * 40 * 2)

template <int M, int N, int K, bool OUTF32, int BMODE>
__global__ __launch_bounds__(128, 3)
void gemm_h(const __half* __restrict__ A, const __half* __restrict__ B, void* Cv)
{
    extern __shared__ __half smg[];
    const uint32_t asb = smem_u32(smg);
    const uint32_t bsb = asb + 3 * 10240;

    const int tid = threadIdx.x, lane = tid & 31, w = tid >> 5;
    const int g = lane >> 2, t = lane & 3;
    const int lr = lane & 7, lb3 = (lane >> 3) & 1, lb4 = (lane >> 4) & 1;
    const int m0w = (w >> 1) * 64, n0w = (w & 1) * 64;
    const int row0 = blockIdx.y * 128, col0 = blockIdx.x * 128;
    const int z = blockIdx.z;

    const __half* Bp = B + (size_t)z * N * K;

    auto LOAD = [&](int k0, int s) {
        const __half* ar = A + (size_t)(row0 + tid) * K + k0;
        const __half* br;
        if (BMODE == 1) {
            const int n  = col0 + tid;
            const int pq = k0 >> 9;
            const int pos = (2 * (n >> 5) + (pq >> 1)) * 64 + 2 * (n & 31) + (pq & 1);
            br = Bp + (size_t)pos * 512 + (k0 & 511);
        } else {
            br = Bp + (size_t)(col0 + tid) * K + k0;
        }
        const uint32_t ad = asb + s * 10240 + tid * 80;
        const uint32_t bd = bsb + s * 10240 + tid * 80;
#pragma unroll
        for (int u = 0; u < 4; u++) {
            cpa16(ad + u * 16, ar + u * 8);
            cpa16(bd + u * 16, br + u * 8);
        }
    };

    float acc[4][8][4];
#pragma unroll
    for (int mt = 0; mt < 4; mt++)
#pragma unroll
        for (int nt = 0; nt < 8; nt++)
#pragma unroll
            for (int r = 0; r < 4; r++) acc[mt][nt][r] = 0.f;

    constexpr int NIT = K / 32;
    LOAD(0, 0); CP_COMMIT();
    LOAD(32, 1); CP_COMMIT();

    for (int i = 0; i < NIT; i++) {
        const int buf = i % 3;
        if (i + 2 < NIT) cp_wait<1>(); else cp_wait<0>();
        __syncthreads();
        if (i + 2 < NIT) { LOAD((i + 2) * 32, (i + 2) % 3); CP_COMMIT(); }

        const uint32_t aB = asb + buf * 10240;
        const uint32_t bB = bsb + buf * 10240;
#pragma unroll
        for (int s = 0; s < 2; s++) {
            uint32_t a[4][4];
#pragma unroll
            for (int mt = 0; mt < 4; mt++)
                ldsm4(a[mt][0], a[mt][1], a[mt][2], a[mt][3],
                      aB + ((m0w + mt * 16 + lb3 * 8 + lr) * 40 + s * 16 + lb4 * 8) * 2);
            uint32_t b[8][2];
#pragma unroll
            for (int np = 0; np < 4; np++) {
                uint32_t r0, r1, r2, r3;
                ldsm4(r0, r1, r2, r3,
                      bB + ((n0w + np * 16 + lb3 * 8 + lr) * 40 + s * 16 + lb4 * 8) * 2);
                b[2 * np][0] = r0; b[2 * np][1] = r2;
                b[2 * np + 1][0] = r1; b[2 * np + 1][1] = r3;
            }
#pragma unroll
            for (int mt = 0; mt < 4; mt++)
#pragma unroll
                for (int nt = 0; nt < 8; nt++)
                    mma16(acc[mt][nt], a[mt], b[nt][0], b[nt][1]);
        }
    }

#pragma unroll
    for (int mt = 0; mt < 4; mt++)
#pragma unroll
        for (int nt = 0; nt < 8; nt++) {
            const int row = row0 + m0w + mt * 16 + g;
            const int col = col0 + n0w + nt * 8 + 2 * t;
            if (OUTF32) {
                float* Cp = (float*)Cv + (size_t)z * M * N;
                float2 v0; v0.x = acc[mt][nt][0]; v0.y = acc[mt][nt][1];
                float2 v1; v1.x = acc[mt][nt][2]; v1.y = acc[mt][nt][3];
                *reinterpret_cast<float2*>(Cp + (size_t)row * N + col)       = v0;
                *reinterpret_cast<float2*>(Cp + (size_t)(row + 8) * N + col) = v1;
            } else {
                __half* Cp = (__half*)Cv + (size_t)z * M * N;
                *reinterpret_cast<uint32_t*>(Cp + (size_t)row * N + col) =
                    packh2(acc[mt][nt][0], acc[mt][nt][1]);
                *reinterpret_cast<uint32_t*>(Cp + (size_t)(row + 8) * N + col) =
                    packh2(acc[mt][nt][2], acc[mt][nt][3]);
            }
        }
}

// ---------------------------------------------------------------------------
// 256-thread GEMM variant (8 warps, warp tile 32x64) — for the kv-GEMM whose
// grid (256 CTAs) underfills the chip at 128 thr. Same tile/pipeline/layout.
// ---------------------------------------------------------------------------
template <int M, int N, int K, bool OUTF32, int BMODE>
__global__ __launch_bounds__(256, 2)
void gemm_h256(const __half* __restrict__ A, const __half* __restrict__ B, void* Cv)
{
    extern __shared__ __half smg[];
    const uint32_t asb = smem_u32(smg);
    const uint32_t bsb = asb + 3 * 10240;

    const int tid = threadIdx.x, lane = tid & 31, w = tid >> 5;   // w 0..7
    const int g = lane >> 2, t = lane & 3;
    const int lr = lane & 7, lb3 = (lane >> 3) & 1, lb4 = (lane >> 4) & 1;
    const int m0w = (w >> 1) * 32, n0w = (w & 1) * 64;
    const int row0 = blockIdx.y * 128, col0 = blockIdx.x * 128;
    const int z = blockIdx.z;

    const __half* Bp = B + (size_t)z * N * K;

    const int lrow = tid >> 1;      // 0..127
    const int hs   = tid & 1;       // 16-half segment

    auto LOAD = [&](int k0, int s) {
        const __half* ar = A + (size_t)(row0 + lrow) * K + k0 + hs * 16;
        const __half* br;
        if (BMODE == 1) {
            const int n  = col0 + lrow;
            const int pq = k0 >> 9;
            const int pos = (2 * (n >> 5) + (pq >> 1)) * 64 + 2 * (n & 31) + (pq & 1);
            br = Bp + (size_t)pos * 512 + (k0 & 511) + hs * 16;
        } else {
            br = Bp + (size_t)(col0 + lrow) * K + k0 + hs * 16;
        }
        const uint32_t ad = asb + s * 10240 + lrow * 80 + hs * 32;
        const uint32_t bd = bsb + s * 10240 + lrow * 80 + hs * 32;
        cpa16(ad,      ar);
        cpa16(ad + 16, ar + 8);
        cpa16(bd,      br);
        cpa16(bd + 16, br + 8);
    };

    float acc[2][8][4];
#pragma unroll
    for (int mt = 0; mt < 2; mt++)
#pragma unroll
        for (int nt = 0; nt < 8; nt++)
#pragma unroll
            for (int r = 0; r < 4; r++) acc[mt][nt][r] = 0.f;

    constexpr int NIT = K / 32;
    LOAD(0, 0); CP_COMMIT();
    LOAD(32, 1); CP_COMMIT();

    for (int i = 0; i < NIT; i++) {
        const int buf = i % 3;
        if (i + 2 < NIT) cp_wait<1>(); else cp_wait<0>();
        __syncthreads();
        if (i + 2 < NIT) { LOAD((i + 2) * 32, (i + 2) % 3); CP_COMMIT(); }

        const uint32_t aB = asb + buf * 10240;
        const uint32_t bB = bsb + buf * 10240;
#pragma unroll
        for (int s = 0; s < 2; s++) {
            uint32_t a[2][4];
#pragma unroll
            for (int mt = 0; mt < 2; mt++)
                ldsm4(a[mt][0], a[mt][1], a[mt][2], a[mt][3],
                      aB + ((m0w + mt * 16 + lb3 * 8 + lr) * 40 + s * 16 + lb4 * 8) * 2);
            uint32_t b[8][2];
#pragma unroll
            for (int np = 0; np < 4; np++) {
                uint32_t r0, r1, r2, r3;
                ldsm4(r0, r1, r2, r3,
                      bB + ((n0w + np * 16 + lb3 * 8 + lr) * 40 + s * 16 + lb4 * 8) * 2);
                b[2 * np][0] = r0; b[2 * np][1] = r2;
                b[2 * np + 1][0] = r1; b[2 * np + 1][1] = r3;
            }
#pragma unroll
            for (int mt = 0; mt < 2; mt++)
#pragma unroll
                for (int nt = 0; nt < 8; nt++)
                    mma16(acc[mt][nt], a[mt], b[nt][0], b[nt][1]);
        }
    }

#pragma unroll
    for (int mt = 0; mt < 2; mt++)
#pragma unroll
        for (int nt = 0; nt < 8; nt++) {
            const int row = row0 + m0w + mt * 16 + g;
            const int col = col0 + n0w + nt * 8 + 2 * t;
            if (OUTF32) {
                float* Cp = (float*)Cv + (size_t)z * M * N;
                float2 v0; v0.x = acc[mt][nt][0]; v0.y = acc[mt][nt][1];
                float2 v1; v1.x = acc[mt][nt][2]; v1.y = acc[mt][nt][3];
                *reinterpret_cast<float2*>(Cp + (size_t)row * N + col)       = v0;
                *reinterpret_cast<float2*>(Cp + (size_t)(row + 8) * N + col) = v1;
            } else {
                __half* Cp = (__half*)Cv + (size_t)z * M * N;
                *reinterpret_cast<uint32_t*>(Cp + (size_t)row * N + col) =
                    packh2(acc[mt][nt][0], acc[mt][nt][1]);
                *reinterpret_cast<uint32_t*>(Cp + (size_t)(row + 8) * N + col) =
                    packh2(acc[mt][nt][2], acc[mt][nt][3]);
            }
        }
}

// ---------------------------------------------------------------------------
// fp16 flash attention (unchanged from 344 µs run).
// ---------------------------------------------------------------------------
#define ATTN_SMEM ((64 * 136 + 4 * 64 * 136) * 2)

__global__ __launch_bounds__(128, 2)
void attn_f16(const __half* __restrict__ Q, const __half* __restrict__ KV,
              __half* __restrict__ OT)
{
    const int bb = blockIdx.z, h = blockIdx.y, i0 = blockIdx.x * 128;
    const int tid = threadIdx.x, lane = tid & 31, w = tid >> 5;
    const int g = lane >> 2, t = lane & 3;
    const int lr = lane & 7, lb3 = (lane >> 3) & 1, lb4 = (lane >> 4) & 1;

    const __half* Qb = Q  + ((size_t)bb * DIM + h * DHEAD) * HW;
    const __half* Kb = KV + ((size_t)bb * 2 * DIM + h * DHEAD) * LKV;
    const __half* Vb = KV + ((size_t)bb * 2 * DIM + DIM + h * DHEAD) * LKV;

    extern __shared__ __half smh[];
    __half* Qs  = smh;
    __half* KV0 = Qs + 64 * 136;
    const uint32_t qb   = smem_u32(Qs);
    const uint32_t kvb0 = smem_u32(KV0);

    auto LOADKV = [&](int j0, int buf) {
        const uint32_t base = kvb0 + buf * (2 * 64 * 136 * 2);
#pragma unroll
        for (int it = 0; it < 16; it++) {
            const int idx = tid + it * 128;
            const int sel = idx >> 10;
            const int r = (idx >> 4) & 63;
            const int c = idx & 15;
            const __half* src = (sel ? Vb : Kb) + (size_t)r * LKV + j0 + c * 8;
            cpa16(base + (sel * 64 * 136 + r * 136 + c * 8) * 2, src);
        }
    };

#pragma unroll
    for (int it = 0; it < 8; it++) {
        const int d = (tid >> 4) + it * 8, col = (tid & 15) * 8;
        cpa16(qb + (d * 136 + col) * 2, Qb + (size_t)d * HW + i0 + col);
    }
    LOADKV(0, 0);
    CP_COMMIT();

    float o[2][8][4];
#pragma unroll
    for (int mt = 0; mt < 2; mt++)
#pragma unroll
        for (int nt = 0; nt < 8; nt++)
#pragma unroll
            for (int r = 0; r < 4; r++) o[mt][nt][r] = 0.f;
    float mrow[4], lrow2[4];
#pragma unroll
    for (int r = 0; r < 4; r++) { mrow[r] = -1e30f; lrow2[r] = 0.f; }

    for (int jc = 0; jc < 8; jc++) {
        const int buf = jc & 1;
        cp_wait<0>();
        __syncthreads();
        if (jc + 1 < 8) { LOADKV((jc + 1) * 128, buf ^ 1); CP_COMMIT(); }

        const uint32_t kb = kvb0 + buf * (2 * 64 * 136 * 2);
        const uint32_t vb = kb + 64 * 136 * 2;

        float s[2][16][4];
#pragma unroll
        for (int mt = 0; mt < 2; mt++)
#pragma unroll
            for (int nt = 0; nt < 16; nt++)
#pragma unroll
                for (int r = 0; r < 4; r++) s[mt][nt][r] = 0.f;

#pragma unroll
        for (int ks = 0; ks < 4; ks++) {
            uint32_t a[2][4];
#pragma unroll
            for (int mt = 0; mt < 2; mt++)
                ldsm4t(a[mt][0], a[mt][1], a[mt][2], a[mt][3],
                       qb + ((16 * ks + lb4 * 8 + lr) * 136 + 32 * w + mt * 16 + lb3 * 8) * 2);
#pragma unroll
            for (int np = 0; np < 8; np++) {
                uint32_t b0, b1, b2, b3;
                ldsm4t(b0, b1, b2, b3,
                       kb + ((16 * ks + lb3 * 8 + lr) * 136 + np * 16 + lb4 * 8) * 2);
                mma16(s[0][2 * np],     a[0], b0, b1);
                mma16(s[0][2 * np + 1], a[0], b2, b3);
                mma16(s[1][2 * np],     a[1], b0, b1);
                mma16(s[1][2 * np + 1], a[1], b2, b3);
            }
        }

        float fac[4];
#pragma unroll
        for (int mt = 0; mt < 2; mt++)
#pragma unroll
            for (int hh = 0; hh < 2; hh++) {
                const int idx = mt * 2 + hh;
                float mx = -1e30f;
#pragma unroll
                for (int nt = 0; nt < 16; nt++) {
                    mx = fmaxf(mx, s[mt][nt][2 * hh]);
                    mx = fmaxf(mx, s[mt][nt][2 * hh + 1]);
                }
                mx = fmaxf(mx, __shfl_xor_sync(0xffffffffu, mx, 1));
                mx = fmaxf(mx, __shfl_xor_sync(0xffffffffu, mx, 2));
                const float mn = fmaxf(mrow[idx], mx);
                fac[idx] = exp2f(mrow[idx] - mn);
                mrow[idx] = mn;
                float ls = 0.f;
#pragma unroll
                for (int nt = 0; nt < 16; nt++) {
                    uint32_t pp = packh2(s[mt][nt][2 * hh] - mn,
                                         s[mt][nt][2 * hh + 1] - mn);
                    asm("ex2.approx.f16x2 %0, %0;" : "+r"(pp));
                    s[mt][nt][2 * hh] = __uint_as_float(pp);
                    const __half2 hp = *reinterpret_cast<const __half2*>(&pp);
                    const float2 fp = __half22float2(hp);
                    ls += fp.x + fp.y;
                }
                lrow2[idx] = lrow2[idx] * fac[idx] + ls;
            }

#pragma unroll
        for (int mt = 0; mt < 2; mt++)
#pragma unroll
            for (int nt = 0; nt < 8; nt++) {
                o[mt][nt][0] *= fac[mt * 2];
                o[mt][nt][1] *= fac[mt * 2];
                o[mt][nt][2] *= fac[mt * 2 + 1];
                o[mt][nt][3] *= fac[mt * 2 + 1];
            }

#pragma unroll
        for (int ks = 0; ks < 8; ks++) {
            uint32_t pa[2][4];
#pragma unroll
            for (int mt = 0; mt < 2; mt++) {
                pa[mt][0] = __float_as_uint(s[mt][2 * ks][0]);
                pa[mt][1] = __float_as_uint(s[mt][2 * ks][2]);
                pa[mt][2] = __float_as_uint(s[mt][2 * ks + 1][0]);
                pa[mt][3] = __float_as_uint(s[mt][2 * ks + 1][2]);
            }
#pragma unroll
            for (int np = 0; np < 4; np++) {
                uint32_t b0, b1, b2, b3;
                ldsm4(b0, b1, b2, b3,
                      vb + ((16 * np + lb4 * 8 + lr) * 136 + 16 * ks + lb3 * 8) * 2);
                mma16(o[0][2 * np],     pa[0], b0, b1);
                mma16(o[0][2 * np + 1], pa[0], b2, b3);
                mma16(o[1][2 * np],     pa[1], b0, b1);
                mma16(o[1][2 * np + 1], pa[1], b2, b3);
            }
        }
    }

    float inv[4];
#pragma unroll
    for (int idx = 0; idx < 4; idx++) {
        float ls = lrow2[idx];
        ls += __shfl_xor_sync(0xffffffffu, ls, 1);
        ls += __shfl_xor_sync(0xffffffffu, ls, 2);
        inv[idx] = 1.f / ls;
    }

    __syncthreads();
    __half* Of = KV0;
#pragma unroll
    for (int mt = 0; mt < 2; mt++) {
        const int row = 32 * w + mt * 16 + g;
#pragma unroll
        for (int nt = 0; nt < 8; nt++) {
            const int d = nt * 8 + 2 * t;
            Of[row * 72 + d]           = __float2half(o[mt][nt][0] * inv[mt * 2]);
            Of[row * 72 + d + 1]       = __float2half(o[mt][nt][1] * inv[mt * 2]);
            Of[(row + 8) * 72 + d]     = __float2half(o[mt][nt][2] * inv[mt * 2 + 1]);
            Of[(row + 8) * 72 + d + 1] = __float2half(o[mt][nt][3] * inv[mt * 2 + 1]);
        }
    }
    __syncthreads();

    __half* dst = OT + ((size_t)bb * HW + i0 + tid) * DIM + h * DHEAD;
#pragma unroll
    for (int u = 0; u < 8; u++)
        reinterpret_cast<uint4*>(dst)[u] =
            *reinterpret_cast<const uint4*>(Of + tid * 72 + u * 8);
}

// ---------------- launch (single stream) ----------------
extern "C" void kernel_launch(void* const* d_in, const int* in_sizes, int n_in,
                              void* d_out, int out_size)
{
    const float* x    = (const float*)d_in[0];
    const float* wq   = (const float*)d_in[1];
    const float* wkv  = (const float*)d_in[2];
    const float* wout = (const float*)d_in[3];
    float* out = (float*)d_out;

    __half *wqh, *wkvh, *woh, *xt, *qh, *kvh, *ot;
    cudaGetSymbolAddress((void**)&wqh,  g_wq);
    cudaGetSymbolAddress((void**)&wkvh, g_wkv);
    cudaGetSymbolAddress((void**)&woh,  g_wo);
    cudaGetSymbolAddress((void**)&xt,   g_xt);
    cudaGetSymbolAddress((void**)&qh,   g_q);
    cudaGetSymbolAddress((void**)&kvh,  g_kv);
    cudaGetSymbolAddress((void**)&ot,   g_ot);

    cudaFuncSetAttribute(attn_f16,
                         cudaFuncAttributeMaxDynamicSharedMemorySize, ATTN_SMEM);
    cudaFuncSetAttribute(gemm_h<512, 4096, 512, false, 0>,
                         cudaFuncAttributeMaxDynamicSharedMemorySize, GEMM_SMEM);
    cudaFuncSetAttribute(gemm_h256<1024, 1024, 2048, false, 1>,
                         cudaFuncAttributeMaxDynamicSharedMemorySize, GEMM_SMEM);
    cudaFuncSetAttribute(gemm_h<512, 4096, 512, true, 0>,
                         cudaFuncAttributeMaxDynamicSharedMemorySize, GEMM_SMEM);

    // prepass: weights (wq scaled, wkv k-reordered) + x^T
    wcvt_kernel<<<(WQ4 + WKV4 + WO4 + 255) / 256, 256>>>(wq, wkv, wout, wqh, wkvh, woh);
    trcvt_kernel<<<dim3(128, 8, BATCH), dim3(32, 8)>>>(x, xt);

    // Q = (0.125*log2e * wq) @ x : [ch][pos] half
    gemm_h<512, 4096, 512, false, 0><<<dim3(32, 4, BATCH), 128, GEMM_SMEM>>>(wqh, xt, qh);
    // KV = wkv' @ im2col(x) — 256-thread variant (fills the chip)
    gemm_h256<1024, 1024, 2048, false, 1><<<dim3(8, 8, BATCH), 256, GEMM_SMEM>>>(wkvh, xt, kvh);
    // attention -> O^T [pos][ch] half
    attn_f16<<<dim3(HW / 128, HEADS, BATCH), 128, ATTN_SMEM>>>(qh, kvh, ot);
    // Y = wout @ O : fp32 out
    gemm_h<512, 4096, 512, true, 0><<<dim3(32, 4, BATCH), 128, GEMM_SMEM>>>(woh, ot, out);
}

// round 16
// speedup vs baseline: 1.3205x; 1.1537x over previous
#include <cuda_runtime.h>
#include <cuda_fp16.h>
#include <cstdint>

#define BATCH 4
#define DIM   512
#define HEADS 8
#define DHEAD 64
#define HW    4096
#define LKV   1024

// fp16 scratch (device globals; allocation-free)
__device__ __half g_wq [512 * 512];
__device__ __half g_wkv[1024 * 2048];   // k-reordered: k' = pq*512 + c
__device__ __half g_wo [512 * 512];
__device__ __half g_xt [BATCH * HW * DIM];     // x^T    [b][pos][ch]
__device__ __half g_q  [BATCH * DIM * HW];     // Q      [b][ch][pos]
__device__ __half g_kv [BATCH * 2 * DIM * LKV];// KV     [b][och][ij]
__device__ __half g_ot [BATCH * HW * DIM];     // attnO^T[b][pos][ch]

// ---------------- helpers ----------------
__device__ __forceinline__ uint32_t packh2(float lo, float hi) {
    uint32_t r;
    asm("cvt.rn.f16x2.f32 %0, %1, %2;" : "=r"(r) : "f"(hi), "f"(lo));
    return r;
}
__device__ __forceinline__ uint32_t smem_u32(const void* p) {
    uint32_t a;
    asm("{ .reg .u64 t; cvta.to.shared.u64 t, %1; cvt.u32.u64 %0, t; }" : "=r"(a) : "l"(p));
    return a;
}
__device__ __forceinline__ void ldsm4(uint32_t& r0, uint32_t& r1, uint32_t& r2, uint32_t& r3,
                                      uint32_t addr) {
    asm volatile("ldmatrix.sync.aligned.m8n8.x4.shared.b16 {%0,%1,%2,%3}, [%4];"
                 : "=r"(r0), "=r"(r1), "=r"(r2), "=r"(r3) : "r"(addr));
}
__device__ __forceinline__ void ldsm4t(uint32_t& r0, uint32_t& r1, uint32_t& r2, uint32_t& r3,
                                       uint32_t addr) {
    asm volatile("ldmatrix.sync.aligned.m8n8.x4.trans.shared.b16 {%0,%1,%2,%3}, [%4];"
                 : "=r"(r0), "=r"(r1), "=r"(r2), "=r"(r3) : "r"(addr));
}
__device__ __forceinline__ void mma16(float* d, const uint32_t* a, uint32_t b0, uint32_t b1) {
    asm volatile("mma.sync.aligned.m16n8k16.row.col.f32.f16.f16.f32 "
        "{%0,%1,%2,%3},{%4,%5,%6,%7},{%8,%9},{%0,%1,%2,%3};"
        : "+f"(d[0]), "+f"(d[1]), "+f"(d[2]), "+f"(d[3])
        : "r"(a[0]), "r"(a[1]), "r"(a[2]), "r"(a[3]), "r"(b0), "r"(b1));
}
__device__ __forceinline__ void cpa16(uint32_t dst, const void* src) {
    asm volatile("cp.async.cg.shared.global [%0], [%1], 16;" :: "r"(dst), "l"(src));
}
#define CP_COMMIT() asm volatile("cp.async.commit_group;" ::: "memory")
template <int NN> __device__ __forceinline__ void cp_wait() {
    asm volatile("cp.async.wait_group %0;" :: "n"(NN) : "memory");
}

// ---------------- prepass ----------------
// Merged weight conversion. wq gets 0.125*log2e folded. wkv is k-REORDERED:
// dst k' = pq*512 + c  <=  src k = c*4 + pq.
#define WQ4   (512 * 512 / 4)
#define WKV4  (1024 * 2048 / 4)
#define WO4   (512 * 512 / 4)
__global__ __launch_bounds__(256)
void wcvt_kernel(const float* __restrict__ wq, const float* __restrict__ wkv,
                 const float* __restrict__ wout,
                 __half* __restrict__ dq, __half* __restrict__ dkv,
                 __half* __restrict__ dwo)
{
    const int i = blockIdx.x * 256 + threadIdx.x;
    if (i < WQ4) {
        const float sc = 0.125f * 1.4426950408889634f;
        float4 v = reinterpret_cast<const float4*>(wq)[i];
        reinterpret_cast<uint2*>(dq)[i] =
            make_uint2(packh2(v.x * sc, v.y * sc), packh2(v.z * sc, v.w * sc));
    } else if (i < WQ4 + WKV4) {
        const int j = i - WQ4;
        const int m = j >> 9, c = j & 511;
        float4 v = reinterpret_cast<const float4*>(wkv)[j];
        __half* drow = dkv + (size_t)m * 2048 + c;
        drow[0]    = __float2half_rn(v.x);   // pq=0
        drow[512]  = __float2half_rn(v.y);   // pq=1
        drow[1024] = __float2half_rn(v.z);   // pq=2
        drow[1536] = __float2half_rn(v.w);   // pq=3
    } else {
        const int j = i - WQ4 - WKV4;
        float4 v = reinterpret_cast<const float4*>(wout)[j];
        reinterpret_cast<uint2*>(dwo)[j] =
            make_uint2(packh2(v.x, v.y), packh2(v.z, v.w));
    }
}

// x [b][512][4096] f32 -> x^T [b][4096][512] half (64ch x 32pos tiles)
__global__ void trcvt_kernel(const float* __restrict__ S, __half* __restrict__ D)
{
    __shared__ float t2[32][65];
    const float* s = S + (size_t)blockIdx.z * DIM * HW;
    __half*      d = D + (size_t)blockIdx.z * HW * DIM;
    const int p0 = blockIdx.x * 32, c0 = blockIdx.y * 64;
    const int tx = threadIdx.x, ty = threadIdx.y;
#pragma unroll
    for (int j = 0; j < 64; j += 8)
        t2[tx][j + ty] = s[(size_t)(c0 + j + ty) * HW + p0 + tx];
    __syncthreads();
#pragma unroll
    for (int j = 0; j < 32; j += 8) {
        const int p = j + ty;
        *reinterpret_cast<uint32_t*>(d + (size_t)(p0 + p) * DIM + c0 + 2 * tx) =
            packh2(t2[p][2 * tx], t2[p][2 * tx + 1]);
    }
}

// ---------------------------------------------------------------------------
// 256-thread all-half GEMM (8 warps, warp tile 32x64, CTA tile 128x128).
// BMODE 0: plain [n][k]. BMODE 1: implicit im2col from x^T (k' = pq*512+c).
// 3-stage cp.async pipeline, ONE barrier per K-iteration (race-free).
// Measured 207 TF/s vs 139 TF/s for the 128-thread variant -> used for ALL
// GEMMs this round.
// ---------------------------------------------------------------------------
#define GEMM_SMEM (3 * 2 * 128 * 40 * 2)

template <int M, int N, int K, bool OUTF32, int BMODE>
__global__ __launch_bounds__(256, 2)
void gemm_h256(const __half* __restrict__ A, const __half* __restrict__ B, void* Cv)
{
    extern __shared__ __half smg[];
    const uint32_t asb = smem_u32(smg);
    const uint32_t bsb = asb + 3 * 10240;

    const int tid = threadIdx.x, lane = tid & 31, w = tid >> 5;   // w 0..7
    const int g = lane >> 2, t = lane & 3;
    const int lr = lane & 7, lb3 = (lane >> 3) & 1, lb4 = (lane >> 4) & 1;
    const int m0w = (w >> 1) * 32, n0w = (w & 1) * 64;
    const int row0 = blockIdx.y * 128, col0 = blockIdx.x * 128;
    const int z = blockIdx.z;

    const __half* Bp = B + (size_t)z * N * K;

    const int lrow = tid >> 1;      // 0..127
    const int hs   = tid & 1;       // 16-half segment

    auto LOAD = [&](int k0, int s) {
        const __half* ar = A + (size_t)(row0 + lrow) * K + k0 + hs * 16;
        const __half* br;
        if (BMODE == 1) {
            const int n  = col0 + lrow;
            const int pq = k0 >> 9;
            const int pos = (2 * (n >> 5) + (pq >> 1)) * 64 + 2 * (n & 31) + (pq & 1);
            br = Bp + (size_t)pos * 512 + (k0 & 511) + hs * 16;
        } else {
            br = Bp + (size_t)(col0 + lrow) * K + k0 + hs * 16;
        }
        const uint32_t ad = asb + s * 10240 + lrow * 80 + hs * 32;
        const uint32_t bd = bsb + s * 10240 + lrow * 80 + hs * 32;
        cpa16(ad,      ar);
        cpa16(ad + 16, ar + 8);
        cpa16(bd,      br);
        cpa16(bd + 16, br + 8);
    };

    float acc[2][8][4];
#pragma unroll
    for (int mt = 0; mt < 2; mt++)
#pragma unroll
        for (int nt = 0; nt < 8; nt++)
#pragma unroll
            for (int r = 0; r < 4; r++) acc[mt][nt][r] = 0.f;

    constexpr int NIT = K / 32;
    LOAD(0, 0); CP_COMMIT();
    LOAD(32, 1); CP_COMMIT();

    for (int i = 0; i < NIT; i++) {
        const int buf = i % 3;
        if (i + 2 < NIT) cp_wait<1>(); else cp_wait<0>();
        __syncthreads();
        if (i + 2 < NIT) { LOAD((i + 2) * 32, (i + 2) % 3); CP_COMMIT(); }

        const uint32_t aB = asb + buf * 10240;
        const uint32_t bB = bsb + buf * 10240;
#pragma unroll
        for (int s = 0; s < 2; s++) {
            uint32_t a[2][4];
#pragma unroll
            for (int mt = 0; mt < 2; mt++)
                ldsm4(a[mt][0], a[mt][1], a[mt][2], a[mt][3],
                      aB + ((m0w + mt * 16 + lb3 * 8 + lr) * 40 + s * 16 + lb4 * 8) * 2);
            uint32_t b[8][2];
#pragma unroll
            for (int np = 0; np < 4; np++) {
                uint32_t r0, r1, r2, r3;
                ldsm4(r0, r1, r2, r3,
                      bB + ((n0w + np * 16 + lb3 * 8 + lr) * 40 + s * 16 + lb4 * 8) * 2);
                b[2 * np][0] = r0; b[2 * np][1] = r2;
                b[2 * np + 1][0] = r1; b[2 * np + 1][1] = r3;
            }
#pragma unroll
            for (int mt = 0; mt < 2; mt++)
#pragma unroll
                for (int nt = 0; nt < 8; nt++)
                    mma16(acc[mt][nt], a[mt], b[nt][0], b[nt][1]);
        }
    }

#pragma unroll
    for (int mt = 0; mt < 2; mt++)
#pragma unroll
        for (int nt = 0; nt < 8; nt++) {
            const int row = row0 + m0w + mt * 16 + g;
            const int col = col0 + n0w + nt * 8 + 2 * t;
            if (OUTF32) {
                float* Cp = (float*)Cv + (size_t)z * M * N;
                float2 v0; v0.x = acc[mt][nt][0]; v0.y = acc[mt][nt][1];
                float2 v1; v1.x = acc[mt][nt][2]; v1.y = acc[mt][nt][3];
                *reinterpret_cast<float2*>(Cp + (size_t)row * N + col)       = v0;
                *reinterpret_cast<float2*>(Cp + (size_t)(row + 8) * N + col) = v1;
            } else {
                __half* Cp = (__half*)Cv + (size_t)z * M * N;
                *reinterpret_cast<uint32_t*>(Cp + (size_t)row * N + col) =
                    packh2(acc[mt][nt][0], acc[mt][nt][1]);
                *reinterpret_cast<uint32_t*>(Cp + (size_t)(row + 8) * N + col) =
                    packh2(acc[mt][nt][2], acc[mt][nt][3]);
            }
        }
}

// ---------------------------------------------------------------------------
// fp16 flash attention (unchanged from 324 µs run).
// ---------------------------------------------------------------------------
#define ATTN_SMEM ((64 * 136 + 4 * 64 * 136) * 2)

__global__ __launch_bounds__(128, 2)
void attn_f16(const __half* __restrict__ Q, const __half* __restrict__ KV,
              __half* __restrict__ OT)
{
    const int bb = blockIdx.z, h = blockIdx.y, i0 = blockIdx.x * 128;
    const int tid = threadIdx.x, lane = tid & 31, w = tid >> 5;
    const int g = lane >> 2, t = lane & 3;
    const int lr = lane & 7, lb3 = (lane >> 3) & 1, lb4 = (lane >> 4) & 1;

    const __half* Qb = Q  + ((size_t)bb * DIM + h * DHEAD) * HW;
    const __half* Kb = KV + ((size_t)bb * 2 * DIM + h * DHEAD) * LKV;
    const __half* Vb = KV + ((size_t)bb * 2 * DIM + DIM + h * DHEAD) * LKV;

    extern __shared__ __half smh[];
    __half* Qs  = smh;
    __half* KV0 = Qs + 64 * 136;
    const uint32_t qb   = smem_u32(Qs);
    const uint32_t kvb0 = smem_u32(KV0);

    auto LOADKV = [&](int j0, int buf) {
        const uint32_t base = kvb0 + buf * (2 * 64 * 136 * 2);
#pragma unroll
        for (int it = 0; it < 16; it++) {
            const int idx = tid + it * 128;
            const int sel = idx >> 10;
            const int r = (idx >> 4) & 63;
            const int c = idx & 15;
            const __half* src = (sel ? Vb : Kb) + (size_t)r * LKV + j0 + c * 8;
            cpa16(base + (sel * 64 * 136 + r * 136 + c * 8) * 2, src);
        }
    };

#pragma unroll
    for (int it = 0; it < 8; it++) {
        const int d = (tid >> 4) + it * 8, col = (tid & 15) * 8;
        cpa16(qb + (d * 136 + col) * 2, Qb + (size_t)d * HW + i0 + col);
    }
    LOADKV(0, 0);
    CP_COMMIT();

    float o[2][8][4];
#pragma unroll
    for (int mt = 0; mt < 2; mt++)
#pragma unroll
        for (int nt = 0; nt < 8; nt++)
#pragma unroll
            for (int r = 0; r < 4; r++) o[mt][nt][r] = 0.f;
    float mrow[4], lrow2[4];
#pragma unroll
    for (int r = 0; r < 4; r++) { mrow[r] = -1e30f; lrow2[r] = 0.f; }

    for (int jc = 0; jc < 8; jc++) {
        const int buf = jc & 1;
        cp_wait<0>();
        __syncthreads();
        if (jc + 1 < 8) { LOADKV((jc + 1) * 128, buf ^ 1); CP_COMMIT(); }

        const uint32_t kb = kvb0 + buf * (2 * 64 * 136 * 2);
        const uint32_t vb = kb + 64 * 136 * 2;

        float s[2][16][4];
#pragma unroll
        for (int mt = 0; mt < 2; mt++)
#pragma unroll
            for (int nt = 0; nt < 16; nt++)
#pragma unroll
                for (int r = 0; r < 4; r++) s[mt][nt][r] = 0.f;

#pragma unroll
        for (int ks = 0; ks < 4; ks++) {
            uint32_t a[2][4];
#pragma unroll
            for (int mt = 0; mt < 2; mt++)
                ldsm4t(a[mt][0], a[mt][1], a[mt][2], a[mt][3],
                       qb + ((16 * ks + lb4 * 8 + lr) * 136 + 32 * w + mt * 16 + lb3 * 8) * 2);
#pragma unroll
            for (int np = 0; np < 8; np++) {
                uint32_t b0, b1, b2, b3;
                ldsm4t(b0, b1, b2, b3,
                       kb + ((16 * ks + lb3 * 8 + lr) * 136 + np * 16 + lb4 * 8) * 2);
                mma16(s[0][2 * np],     a[0], b0, b1);
                mma16(s[0][2 * np + 1], a[0], b2, b3);
                mma16(s[1][2 * np],     a[1], b0, b1);
                mma16(s[1][2 * np + 1], a[1], b2, b3);
            }
        }

        float fac[4];
#pragma unroll
        for (int mt = 0; mt < 2; mt++)
#pragma unroll
            for (int hh = 0; hh < 2; hh++) {
                const int idx = mt * 2 + hh;
                float mx = -1e30f;
#pragma unroll
                for (int nt = 0; nt < 16; nt++) {
                    mx = fmaxf(mx, s[mt][nt][2 * hh]);
                    mx = fmaxf(mx, s[mt][nt][2 * hh + 1]);
                }
                mx = fmaxf(mx, __shfl_xor_sync(0xffffffffu, mx, 1));
                mx = fmaxf(mx, __shfl_xor_sync(0xffffffffu, mx, 2));
                const float mn = fmaxf(mrow[idx], mx);
                fac[idx] = exp2f(mrow[idx] - mn);
                mrow[idx] = mn;
                float ls = 0.f;
#pragma unroll
                for (int nt = 0; nt < 16; nt++) {
                    uint32_t pp = packh2(s[mt][nt][2 * hh] - mn,
                                         s[mt][nt][2 * hh + 1] - mn);
                    asm("ex2.approx.f16x2 %0, %0;" : "+r"(pp));
                    s[mt][nt][2 * hh] = __uint_as_float(pp);
                    const __half2 hp = *reinterpret_cast<const __half2*>(&pp);
                    const float2 fp = __half22float2(hp);
                    ls += fp.x + fp.y;
                }
                lrow2[idx] = lrow2[idx] * fac[idx] + ls;
            }

#pragma unroll
        for (int mt = 0; mt < 2; mt++)
#pragma unroll
            for (int nt = 0; nt < 8; nt++) {
                o[mt][nt][0] *= fac[mt * 2];
                o[mt][nt][1] *= fac[mt * 2];
                o[mt][nt][2] *= fac[mt * 2 + 1];
                o[mt][nt][3] *= fac[mt * 2 + 1];
            }

#pragma unroll
        for (int ks = 0; ks < 8; ks++) {
            uint32_t pa[2][4];
#pragma unroll
            for (int mt = 0; mt < 2; mt++) {
                pa[mt][0] = __float_as_uint(s[mt][2 * ks][0]);
                pa[mt][1] = __float_as_uint(s[mt][2 * ks][2]);
                pa[mt][2] = __float_as_uint(s[mt][2 * ks + 1][0]);
                pa[mt][3] = __float_as_uint(s[mt][2 * ks + 1][2]);
            }
#pragma unroll
            for (int np = 0; np < 4; np++) {
                uint32_t b0, b1, b2, b3;
                ldsm4(b0, b1, b2, b3,
                      vb + ((16 * np + lb4 * 8 + lr) * 136 + 16 * ks + lb3 * 8) * 2);
                mma16(o[0][2 * np],     pa[0], b0, b1);
                mma16(o[0][2 * np + 1], pa[0], b2, b3);
                mma16(o[1][2 * np],     pa[1], b0, b1);
                mma16(o[1][2 * np + 1], pa[1], b2, b3);
            }
        }
    }

    float inv[4];
#pragma unroll
    for (int idx = 0; idx < 4; idx++) {
        float ls = lrow2[idx];
        ls += __shfl_xor_sync(0xffffffffu, ls, 1);
        ls += __shfl_xor_sync(0xffffffffu, ls, 2);
        inv[idx] = 1.f / ls;
    }

    __syncthreads();
    __half* Of = KV0;
#pragma unroll
    for (int mt = 0; mt < 2; mt++) {
        const int row = 32 * w + mt * 16 + g;
#pragma unroll
        for (int nt = 0; nt < 8; nt++) {
            const int d = nt * 8 + 2 * t;
            Of[row * 72 + d]           = __float2half(o[mt][nt][0] * inv[mt * 2]);
            Of[row * 72 + d + 1]       = __float2half(o[mt][nt][1] * inv[mt * 2]);
            Of[(row + 8) * 72 + d]     = __float2half(o[mt][nt][2] * inv[mt * 2 + 1]);
            Of[(row + 8) * 72 + d + 1] = __float2half(o[mt][nt][3] * inv[mt * 2 + 1]);
        }
    }
    __syncthreads();

    __half* dst = OT + ((size_t)bb * HW + i0 + tid) * DIM + h * DHEAD;
#pragma unroll
    for (int u = 0; u < 8; u++)
        reinterpret_cast<uint4*>(dst)[u] =
            *reinterpret_cast<const uint4*>(Of + tid * 72 + u * 8);
}

// ---------------- launch (single stream) ----------------
extern "C" void kernel_launch(void* const* d_in, const int* in_sizes, int n_in,
                              void* d_out, int out_size)
{
    const float* x    = (const float*)d_in[0];
    const float* wq   = (const float*)d_in[1];
    const float* wkv  = (const float*)d_in[2];
    const float* wout = (const float*)d_in[3];
    float* out = (float*)d_out;

    __half *wqh, *wkvh, *woh, *xt, *qh, *kvh, *ot;
    cudaGetSymbolAddress((void**)&wqh,  g_wq);
    cudaGetSymbolAddress((void**)&wkvh, g_wkv);
    cudaGetSymbolAddress((void**)&woh,  g_wo);
    cudaGetSymbolAddress((void**)&xt,   g_xt);
    cudaGetSymbolAddress((void**)&qh,   g_q);
    cudaGetSymbolAddress((void**)&kvh,  g_kv);
    cudaGetSymbolAddress((void**)&ot,   g_ot);

    cudaFuncSetAttribute(attn_f16,
                         cudaFuncAttributeMaxDynamicSharedMemorySize, ATTN_SMEM);
    cudaFuncSetAttribute(gemm_h256<512, 4096, 512, false, 0>,
                         cudaFuncAttributeMaxDynamicSharedMemorySize, GEMM_SMEM);
    cudaFuncSetAttribute(gemm_h256<1024, 1024, 2048, false, 1>,
                         cudaFuncAttributeMaxDynamicSharedMemorySize, GEMM_SMEM);
    cudaFuncSetAttribute(gemm_h256<512, 4096, 512, true, 0>,
                         cudaFuncAttributeMaxDynamicSharedMemorySize, GEMM_SMEM);

    // prepass: weights (wq scaled, wkv k-reordered) + x^T
    wcvt_kernel<<<(WQ4 + WKV4 + WO4 + 255) / 256, 256>>>(wq, wkv, wout, wqh, wkvh, woh);
    trcvt_kernel<<<dim3(128, 8, BATCH), dim3(32, 8)>>>(x, xt);

    // Q = (0.125*log2e * wq) @ x : [ch][pos] half
    gemm_h256<512, 4096, 512, false, 0><<<dim3(32, 4, BATCH), 256, GEMM_SMEM>>>(wqh, xt, qh);
    // KV = wkv' @ im2col(x) — implicit im2col from x^T
    gemm_h256<1024, 1024, 2048, false, 1><<<dim3(8, 8, BATCH), 256, GEMM_SMEM>>>(wkvh, xt, kvh);
    // attention -> O^T [pos][ch] half
    attn_f16<<<dim3(HW / 128, HEADS, BATCH), 128, ATTN_SMEM>>>(qh, kvh, ot);
    // Y = wout @ O : fp32 out
    gemm_h256<512, 4096, 512, true, 0><<<dim3(32, 4, BATCH), 256, GEMM_SMEM>>>(woh, ot, out);
}